// round 17
// baseline (speedup 1.0000x reference)
#include <cuda_runtime.h>
#include <cuda_bf16.h>
#include <cstdint>
#include <math.h>

// ---------------------------------------------------------------------------
// AV_Attention via legacy mma.sync bf16x3 (2-split, 3-product) emulated-fp32.
//   Q  = img @ q_w^T + q_b                      [16384,1024]
//   K  = text @ k_w^T + k_b                     [16384,1024]
//   VT = v_w @ text^T + v_b(row)  per batch     [8,1024,2048]  (V transposed)
//   S  = Q @ K^T per batch                      [8,2048,2048]
//   A  = softmax(S) * 1/32  (in place)
//   out = A @ VT^T per batch ; feature = out + text
// All GEMMs: C[m][n] = sum_k A[m][k] * B[n][k]  (k contiguous everywhere).
// GEMM core: CTA 128x256, warp 64x64, BK=32 fp32, cp.async 2-stage pipeline,
// in-kernel fp32 -> (hi,lo) bf16 split, 3-product MMA accumulation.
// ---------------------------------------------------------------------------

static __device__ float g_Q[16777216];   // 64 MB
static __device__ float g_K[16777216];   // 64 MB
static __device__ float g_VT[16777216];  // 64 MB  [8][1024 v][2048 s]
static __device__ float g_S[33554432];   // 128 MB scores/atten

// ============================ helpers ======================================
__device__ __forceinline__ uint32_t smem_u32(const void* p) {
    uint32_t a;
    asm("{ .reg .u64 t; cvta.to.shared.u64 t, %1; cvt.u32.u64 %0, t; }"
        : "=r"(a) : "l"(p));
    return a;
}

__device__ __forceinline__ void ldsm4(uint32_t* r, uint32_t addr) {
    asm volatile("ldmatrix.sync.aligned.m8n8.x4.shared.b16 {%0,%1,%2,%3}, [%4];"
                 : "=r"(r[0]), "=r"(r[1]), "=r"(r[2]), "=r"(r[3]) : "r"(addr));
}

__device__ __forceinline__ void mma16816(float* d, const uint32_t* a,
                                         uint32_t b0, uint32_t b1) {
    asm volatile(
        "mma.sync.aligned.m16n8k16.row.col.f32.bf16.bf16.f32 "
        "{%0,%1,%2,%3}, {%4,%5,%6,%7}, {%8,%9}, {%0,%1,%2,%3};"
        : "+f"(d[0]), "+f"(d[1]), "+f"(d[2]), "+f"(d[3])
        : "r"(a[0]), "r"(a[1]), "r"(a[2]), "r"(a[3]), "r"(b0), "r"(b1));
}

#define CP_ASYNC16(dst, src) \
    asm volatile("cp.async.cg.shared.global [%0], [%1], 16;" \
                 :: "r"(dst), "l"(src))
#define CP_COMMIT() asm volatile("cp.async.commit_group;" ::: "memory")
#define CP_WAIT1()  asm volatile("cp.async.wait_group 1;" ::: "memory")

// fp32 -> (hi bf16, lo bf16) split for 8 consecutive elements
__device__ __forceinline__ void split8(const float4& v0, const float4& v1,
                                       uint4& hi, uint4& lo) {
    float f[8] = {v0.x, v0.y, v0.z, v0.w, v1.x, v1.y, v1.z, v1.w};
    uint32_t h[4], l[4];
#pragma unroll
    for (int j = 0; j < 4; ++j) {
        float a = f[2 * j], b = f[2 * j + 1];
        uint32_t hp;
        asm("cvt.rn.bf16x2.f32 %0, %1, %2;" : "=r"(hp) : "f"(b), "f"(a));
        float ra = __uint_as_float(hp << 16);
        float rb = __uint_as_float(hp & 0xFFFF0000u);
        float la = a - ra, lb = b - rb;
        uint32_t lp;
        asm("cvt.rn.bf16x2.f32 %0, %1, %2;" : "=r"(lp) : "f"(lb), "f"(la));
        h[j] = hp; l[j] = lp;
    }
    hi = make_uint4(h[0], h[1], h[2], h[3]);
    lo = make_uint4(l[0], l[1], l[2], l[3]);
}

// ============================ GEMM kernel ==================================
// SMEM map (bytes):
//   bf16 buf b (b=0,1) @ b*49152:
//     A_hi @ +0 (8K)  A_lo @ +8192  B_hi @ +16384 (16K)  B_lo @ +32768 (16K)
//   fp32 stage s @ 98304 + s*55296:
//     A[128][36] fl (pitch 144B) @ +0 (18432)  B[256][36] @ +18432 (36864)
//   epilogue: fp32 C tile [128][260] over the whole region.
constexpr int SMEM_BYTES = 208896;
constexpr uint32_t BUF_STRIDE = 49152;
constexpr uint32_t OFF_STAGE = 98304;
constexpr uint32_t STAGE_STRIDE = 55296;
constexpr uint32_t STB_OFF = 18432;     // B stage within a stage
constexpr int ST_PITCH = 144;           // bytes per fp32 stage row (36 floats)

// swizzled byte offset within a [rows][32 bf16] tile (64B rows)
__device__ __forceinline__ uint32_t swz(int row, int colb) {
    return (uint32_t)(row * 64 + (colb ^ ((row & 6) << 3)));
}

// BIASMODE: 0 = none, 1 = per-column, 2 = per-row
template <int BIASMODE, bool AVEPI>
__global__ void __launch_bounds__(256, 1)
tc_gemm(const float* __restrict__ A, const float* __restrict__ B,
        const float* __restrict__ bias, float* __restrict__ C,
        const float* __restrict__ text, float* __restrict__ feat,
        int K, int lda, int ldb, int ldc,
        long long sA, long long sB, long long sC)
{
    extern __shared__ char smem[];
    const uint32_t sb = smem_u32(smem);
    const int tid = threadIdx.x;
    const int lane = tid & 31, warp = tid >> 5;
    const int bx = blockIdx.x, by = blockIdx.y, z = blockIdx.z;

    A += (long long)z * sA;
    B += (long long)z * sB;
    C += (long long)z * sC;
    const float* textz = nullptr;
    float* featz = nullptr;
    if (AVEPI) { textz = text + (long long)z * sC; featz = feat + (long long)z * sC; }

    // ---- loader/convert assignment: 8-float groups, koct shared ----
    const int arow0 = tid >> 2;            // 0..63  (A rows arow0, arow0+64)
    const int koct  = tid & 3;             // 0..3   (k offset = koct*8 floats)
    const float* aG0 = A + (long long)(by * 128 + arow0) * lda + koct * 8;
    const float* aG1 = aG0 + 64LL * lda;
    const float* bG0 = B + (long long)(bx * 256 + arow0) * ldb + koct * 8;
    // B rows: arow0, +64, +128, +192

    const uint32_t stA_off = (uint32_t)(arow0 * ST_PITCH + koct * 32);
    const uint32_t stB_off = STB_OFF + (uint32_t)(arow0 * ST_PITCH + koct * 32);

    // bf16 STS offsets (within A / B regions of a buffer)
    const uint32_t aS0 = swz(arow0, koct * 16);
    const uint32_t aS1 = swz(arow0 + 64, koct * 16);
    uint32_t bS[4];
#pragma unroll
    for (int i = 0; i < 4; ++i) bS[i] = swz(arow0 + 64 * i, koct * 16);

    // ---- ldmatrix per-lane offsets ----
    const int wm = (warp >> 2) * 64;      // warp M offset (0/64)
    const int wn = (warp & 3) * 64;       // warp N offset (0..192)
    const int a_r = lane & 15;
    const int a_cb = (lane >> 4) << 4;
    const int b_r = ((lane >> 4) << 3) + (lane & 7);
    const int b_cb = (lane & 8) ? 16 : 0;

    uint32_t a_off[4][2], b_off[4][2];
#pragma unroll
    for (int mt = 0; mt < 4; ++mt)
#pragma unroll
        for (int ks = 0; ks < 2; ++ks)
            a_off[mt][ks] = sb + swz(wm + mt * 16 + a_r, ks * 32 + a_cb);
#pragma unroll
    for (int ng = 0; ng < 4; ++ng)
#pragma unroll
        for (int ks = 0; ks < 2; ++ks)
            b_off[ng][ks] = sb + 16384u + swz(wn + ng * 16 + b_r, ks * 32 + b_cb);

    float acc[4][8][4];
#pragma unroll
    for (int i = 0; i < 4; ++i)
#pragma unroll
        for (int j = 0; j < 8; ++j)
#pragma unroll
            for (int c = 0; c < 4; ++c) acc[i][j][c] = 0.0f;

    const int nk = K >> 5;

    // ---- cp.async issue for chunk kt into stage s ----
    auto issue = [&](int kt, int s) {
        if (kt < nk) {
            const uint32_t st = sb + OFF_STAGE + (uint32_t)s * STAGE_STRIDE;
            const int k0 = kt << 5;
            CP_ASYNC16(st + stA_off,      aG0 + k0);
            CP_ASYNC16(st + stA_off + 16, aG0 + k0 + 4);
            CP_ASYNC16(st + stA_off + 64 * ST_PITCH,      aG1 + k0);
            CP_ASYNC16(st + stA_off + 64 * ST_PITCH + 16, aG1 + k0 + 4);
#pragma unroll
            for (int i = 0; i < 4; ++i) {
                const float* g = bG0 + (long long)(64 * i) * ldb + k0;
                CP_ASYNC16(st + stB_off + i * 64 * ST_PITCH,      g);
                CP_ASYNC16(st + stB_off + i * 64 * ST_PITCH + 16, g + 4);
            }
        }
        CP_COMMIT();
    };

    issue(0, 0);
    issue(1, 1);

    for (int kt = 0; kt < nk; ++kt) {
        const int s = kt & 1;
        const uint32_t bo = (uint32_t)s * BUF_STRIDE;
        CP_WAIT1();

        // ---- convert own granules: fp32 stage -> bf16 hi/lo ----
        {
            char* st = smem + OFF_STAGE + (uint32_t)s * STAGE_STRIDE;
            char* buf = smem + bo;
            float4 v0, v1; uint4 hi, lo;
            // A row 0
            v0 = *reinterpret_cast<const float4*>(st + stA_off);
            v1 = *reinterpret_cast<const float4*>(st + stA_off + 16);
            split8(v0, v1, hi, lo);
            *reinterpret_cast<uint4*>(buf + aS0) = hi;
            *reinterpret_cast<uint4*>(buf + 8192 + aS0) = lo;
            // A row 1
            v0 = *reinterpret_cast<const float4*>(st + stA_off + 64 * ST_PITCH);
            v1 = *reinterpret_cast<const float4*>(st + stA_off + 64 * ST_PITCH + 16);
            split8(v0, v1, hi, lo);
            *reinterpret_cast<uint4*>(buf + aS1) = hi;
            *reinterpret_cast<uint4*>(buf + 8192 + aS1) = lo;
            // B rows 0..3
#pragma unroll
            for (int i = 0; i < 4; ++i) {
                v0 = *reinterpret_cast<const float4*>(st + stB_off + i * 64 * ST_PITCH);
                v1 = *reinterpret_cast<const float4*>(st + stB_off + i * 64 * ST_PITCH + 16);
                split8(v0, v1, hi, lo);
                *reinterpret_cast<uint4*>(buf + 16384 + bS[i]) = hi;
                *reinterpret_cast<uint4*>(buf + 32768 + bS[i]) = lo;
            }
        }
        __syncthreads();

        issue(kt + 2, s);

        // ---- MMA: 2 k16-steps x (8 A-ldsm + 4x(2 B-ldsm + 24 MMA)) ----
#pragma unroll
        for (int ks = 0; ks < 2; ++ks) {
            uint32_t Ah[4][4], Al[4][4];
#pragma unroll
            for (int mt = 0; mt < 4; ++mt) {
                ldsm4(Ah[mt], a_off[mt][ks] + bo);
                ldsm4(Al[mt], a_off[mt][ks] + bo + 8192u);
            }
#pragma unroll
            for (int ng = 0; ng < 4; ++ng) {
                uint32_t Bh[4], Bl[4];
                ldsm4(Bh, b_off[ng][ks] + bo);
                ldsm4(Bl, b_off[ng][ks] + bo + 16384u);
#pragma unroll
                for (int p = 0; p < 3; ++p) {
#pragma unroll
                    for (int mt = 0; mt < 4; ++mt) {
#pragma unroll
                        for (int t = 0; t < 2; ++t) {
                            const uint32_t* af = (p == 2) ? Al[mt] : Ah[mt];
                            const uint32_t* bf = (p == 1) ? Bl : Bh;
                            mma16816(acc[mt][ng * 2 + t], af, bf[t * 2], bf[t * 2 + 1]);
                        }
                    }
                }
            }
        }
        __syncthreads();
    }

    // ---- epilogue: stage whole C tile [128][260] fp32, coalesced write ----
    float* Cs = reinterpret_cast<float*>(smem);
#pragma unroll
    for (int mt = 0; mt < 4; ++mt) {
#pragma unroll
        for (int nt = 0; nt < 8; ++nt) {
            const int m = wm + mt * 16 + (lane >> 2);
            const int n = wn + nt * 8 + (lane & 3) * 2;
            *reinterpret_cast<float2*>(&Cs[m * 260 + n]) =
                make_float2(acc[mt][nt][0], acc[mt][nt][1]);
            *reinterpret_cast<float2*>(&Cs[(m + 8) * 260 + n]) =
                make_float2(acc[mt][nt][2], acc[mt][nt][3]);
        }
    }
    __syncthreads();

    {
        const int row = tid >> 1;
        const int chalf = (tid & 1) * 128;
        const long long grow = (long long)(by * 128 + row) * ldc + bx * 256 + chalf;
        float rbias = 0.0f;
        if (BIASMODE == 2) rbias = bias[by * 128 + row];
#pragma unroll
        for (int j = 0; j < 128; j += 4) {
            float4 v = *reinterpret_cast<const float4*>(&Cs[row * 260 + chalf + j]);
            if (BIASMODE == 1) {
                float4 bb = *reinterpret_cast<const float4*>(bias + bx * 256 + chalf + j);
                v.x += bb.x; v.y += bb.y; v.z += bb.z; v.w += bb.w;
            } else if (BIASMODE == 2) {
                v.x += rbias; v.y += rbias; v.z += rbias; v.w += rbias;
            }
            *reinterpret_cast<float4*>(C + grow + j) = v;
            if (AVEPI) {
                float4 t = *reinterpret_cast<const float4*>(textz + grow + j);
                *reinterpret_cast<float4*>(featz + grow + j) =
                    make_float4(v.x + t.x, v.y + t.y, v.z + t.z, v.w + t.w);
            }
        }
    }
}

// ============================ Softmax ======================================
// Row softmax over 2048 cols, in place, fused * (1/sqrt(1024)).
__global__ void __launch_bounds__(256) softmax_k(float* __restrict__ Sm)
{
    __shared__ float red[32];
    const long long row = blockIdx.x;
    float* p = Sm + row * 2048;
    const int t = threadIdx.x;
    const int lane = t & 31, w = t >> 5;

    float4 v0 = reinterpret_cast<const float4*>(p)[t];
    float4 v1 = reinterpret_cast<const float4*>(p)[t + 256];

    float m = fmaxf(fmaxf(fmaxf(v0.x, v0.y), fmaxf(v0.z, v0.w)),
                    fmaxf(fmaxf(v1.x, v1.y), fmaxf(v1.z, v1.w)));
#pragma unroll
    for (int o = 16; o > 0; o >>= 1) m = fmaxf(m, __shfl_xor_sync(0xFFFFFFFFu, m, o));
    if (lane == 0) red[w] = m;
    __syncthreads();
    if (t < 32) {
        float x = (t < 8) ? red[t] : -3.4e38f;
#pragma unroll
        for (int o = 4; o > 0; o >>= 1) x = fmaxf(x, __shfl_xor_sync(0xFFFFFFFFu, x, o));
        if (t == 0) red[0] = x;
    }
    __syncthreads();
    m = red[0];
    __syncthreads();

    float e[8];
    e[0] = expf(v0.x - m); e[1] = expf(v0.y - m); e[2] = expf(v0.z - m); e[3] = expf(v0.w - m);
    e[4] = expf(v1.x - m); e[5] = expf(v1.y - m); e[6] = expf(v1.z - m); e[7] = expf(v1.w - m);
    float s = ((e[0] + e[1]) + (e[2] + e[3])) + ((e[4] + e[5]) + (e[6] + e[7]));
#pragma unroll
    for (int o = 16; o > 0; o >>= 1) s += __shfl_xor_sync(0xFFFFFFFFu, s, o);
    if (lane == 0) red[w] = s;
    __syncthreads();
    if (t < 32) {
        float x = (t < 8) ? red[t] : 0.0f;
#pragma unroll
        for (int o = 4; o > 0; o >>= 1) x += __shfl_xor_sync(0xFFFFFFFFu, x, o);
        if (t == 0) red[0] = x;
    }
    __syncthreads();
    s = red[0];

    const float inv = 0.03125f / s;
    reinterpret_cast<float4*>(p)[t]       = make_float4(e[0]*inv, e[1]*inv, e[2]*inv, e[3]*inv);
    reinterpret_cast<float4*>(p)[t + 256] = make_float4(e[4]*inv, e[5]*inv, e[6]*inv, e[7]*inv);
}

// ============================ Launch =======================================
extern "C" void kernel_launch(void* const* d_in, const int* in_sizes, int n_in,
                              void* d_out, int out_size)
{
    const float* img  = (const float*)d_in[0];
    const float* text = (const float*)d_in[1];
    const float* q_w  = (const float*)d_in[2];
    const float* q_b  = (const float*)d_in[3];
    const float* k_w  = (const float*)d_in[4];
    const float* k_b  = (const float*)d_in[5];
    const float* v_w  = (const float*)d_in[6];
    const float* v_b  = (const float*)d_in[7];
    float* out = (float*)d_out;

    float *gq, *gk, *gvt, *gs;
    cudaGetSymbolAddress((void**)&gq,  g_Q);
    cudaGetSymbolAddress((void**)&gk,  g_K);
    cudaGetSymbolAddress((void**)&gvt, g_VT);
    cudaGetSymbolAddress((void**)&gs,  g_S);

    cudaFuncSetAttribute(tc_gemm<1, false>, cudaFuncAttributeMaxDynamicSharedMemorySize, SMEM_BYTES);
    cudaFuncSetAttribute(tc_gemm<2, false>, cudaFuncAttributeMaxDynamicSharedMemorySize, SMEM_BYTES);
    cudaFuncSetAttribute(tc_gemm<0, false>, cudaFuncAttributeMaxDynamicSharedMemorySize, SMEM_BYTES);
    cudaFuncSetAttribute(tc_gemm<0, true>,  cudaFuncAttributeMaxDynamicSharedMemorySize, SMEM_BYTES);

    // Q = img @ q_w^T + q_b   : M=16384, N=1024, K=1024
    tc_gemm<1, false><<<dim3(4, 128, 1), 256, SMEM_BYTES>>>(
        img, q_w, q_b, gq, nullptr, nullptr, 1024, 1024, 1024, 1024, 0, 0, 0);
    // K = text @ k_w^T + k_b
    tc_gemm<1, false><<<dim3(4, 128, 1), 256, SMEM_BYTES>>>(
        text, k_w, k_b, gk, nullptr, nullptr, 1024, 1024, 1024, 1024, 0, 0, 0);
    // VT[z] = v_w @ text[z]^T + v_b(row) : M=1024, N=2048, K=1024, 8 batches
    tc_gemm<2, false><<<dim3(8, 8, 8), 256, SMEM_BYTES>>>(
        v_w, text, v_b, gvt, nullptr, nullptr, 1024, 1024, 1024, 2048,
        0, 2048LL * 1024, 1024LL * 2048);
    // S[z] = Q[z] @ K[z]^T : M=2048, N=2048, K=1024, 8 batches
    tc_gemm<0, false><<<dim3(8, 16, 8), 256, SMEM_BYTES>>>(
        gq, gk, nullptr, gs, nullptr, nullptr, 1024, 1024, 1024, 2048,
        2048LL * 1024, 2048LL * 1024, 2048LL * 2048);
    // softmax * 1/32, in place
    softmax_k<<<8 * 2048, 256>>>(gs);
    // out[z] = A[z] @ VT[z]^T ; feature = out + text : M=2048, N=1024, K=2048
    tc_gemm<0, true><<<dim3(4, 16, 8), 256, SMEM_BYTES>>>(
        gs, gvt, nullptr, out, text, out + 16777216LL, 2048, 2048, 2048, 1024,
        2048LL * 2048, 1024LL * 2048, 2048LL * 1024);

    (void)in_sizes; (void)n_in; (void)out_size;
}